// round 4
// baseline (speedup 1.0000x reference)
#include <cuda_runtime.h>
#include <math.h>
#include <stdint.h>

#define BS 8
#define NN 2048
#define IN_F 256
#define OUT_F 128
#define NROWS (BS * NN)   // 16384

// ---------------- scratch (static __device__, no allocations) ----------------
__device__ float g_WT[IN_F * OUT_F];             // W transposed: [k][o]
__device__ float g_nodes[(size_t)NROWS * OUT_F]; // 8 MB, tf32-rounded values
__device__ float g_fsrc[NROWS];
__device__ float g_fdstb[NROWS];                 // f_dst + a_b folded

// ---------------- kernel 0: transpose W (128x256 -> 256x128) ----------------
__global__ void transpose_W_kernel(const float* __restrict__ W) {
    int i = blockIdx.x * blockDim.x + threadIdx.x;
    int o = i >> 8;
    int k = i & 255;
    g_WT[k * OUT_F + o] = W[i];
}

// ---------------- kernel 1: nodes = X @ W^T + b, plus f_src/f_dst ----------------
__global__ __launch_bounds__(256) void node_transform_kernel(
    const float* __restrict__ X,
    const float* __restrict__ Wb,
    const float* __restrict__ aw,
    const float* __restrict__ ab)
{
    __shared__ float sIn[32 * 64];
    __shared__ float sW[64 * 128];

    const int t  = threadIdx.x;
    const int tx = t & 31;
    const int ty = t >> 5;
    const int R0 = blockIdx.x * 32;

    float acc[4][4];
    #pragma unroll
    for (int i = 0; i < 4; i++)
        #pragma unroll
        for (int j = 0; j < 4; j++) acc[i][j] = 0.f;

    for (int kc = 0; kc < 4; kc++) {
        const int k0 = kc * 64;
        __syncthreads();
        #pragma unroll
        for (int j = 0; j < 2; j++) {
            int f4 = t + 256 * j;
            int rr = f4 >> 4, c4 = f4 & 15;
            *(float4*)&sIn[rr * 64 + c4 * 4] =
                *(const float4*)&X[(size_t)(R0 + rr) * IN_F + k0 + c4 * 4];
        }
        #pragma unroll
        for (int j = 0; j < 8; j++) {
            int f4 = t + 256 * j;
            int kk = f4 >> 5, o4 = f4 & 31;
            *(float4*)&sW[kk * 128 + o4 * 4] =
                *(const float4*)&g_WT[(size_t)(k0 + kk) * OUT_F + o4 * 4];
        }
        __syncthreads();

        #pragma unroll
        for (int k4 = 0; k4 < 16; k4++) {
            float4 iv[4];
            #pragma unroll
            for (int i = 0; i < 4; i++)
                iv[i] = *(float4*)&sIn[(ty * 4 + i) * 64 + k4 * 4];
            #pragma unroll
            for (int kk = 0; kk < 4; kk++) {
                float4 wv = *(float4*)&sW[(k4 * 4 + kk) * 128 + tx * 4];
                #pragma unroll
                for (int i = 0; i < 4; i++) {
                    float xv = (kk == 0) ? iv[i].x : (kk == 1) ? iv[i].y
                             : (kk == 2) ? iv[i].z : iv[i].w;
                    acc[i][0] = fmaf(xv, wv.x, acc[i][0]);
                    acc[i][1] = fmaf(xv, wv.y, acc[i][1]);
                    acc[i][2] = fmaf(xv, wv.z, acc[i][2]);
                    acc[i][3] = fmaf(xv, wv.w, acc[i][3]);
                }
            }
        }
    }

    float bb[4], a1[4], a2[4];
    #pragma unroll
    for (int j = 0; j < 4; j++) {
        bb[j] = Wb[tx * 4 + j];
        a1[j] = aw[tx * 4 + j];
        a2[j] = aw[OUT_F + tx * 4 + j];
    }
    const float abv = ab[0];

    #pragma unroll
    for (int i = 0; i < 4; i++) {
        #pragma unroll
        for (int j = 0; j < 4; j++) acc[i][j] += bb[j];
        const int row = R0 + ty * 4 + i;

        float ps = acc[i][0]*a1[0] + acc[i][1]*a1[1] + acc[i][2]*a1[2] + acc[i][3]*a1[3];
        float pd = acc[i][0]*a2[0] + acc[i][1]*a2[1] + acc[i][2]*a2[2] + acc[i][3]*a2[3];
        #pragma unroll
        for (int off = 16; off > 0; off >>= 1) {
            ps += __shfl_xor_sync(0xffffffffu, ps, off);
            pd += __shfl_xor_sync(0xffffffffu, pd, off);
        }
        if (tx == 0) {
            g_fsrc[row]  = ps;
            g_fdstb[row] = pd + abv;
        }

        uint4 sv;
        asm("cvt.rna.tf32.f32 %0, %1;" : "=r"(sv.x) : "f"(acc[i][0]));
        asm("cvt.rna.tf32.f32 %0, %1;" : "=r"(sv.y) : "f"(acc[i][1]));
        asm("cvt.rna.tf32.f32 %0, %1;" : "=r"(sv.z) : "f"(acc[i][2]));
        asm("cvt.rna.tf32.f32 %0, %1;" : "=r"(sv.w) : "f"(acc[i][3]));
        *(uint4*)&g_nodes[(size_t)row * OUT_F + tx * 4] = sv;
    }
}

// ---------------- kernel 2: masked softmax + tf32 MMA PV, 128-row blocks ----------
// grid (16, 8) = 128 blocks (one wave), 256 threads (8 warps).
// Block: 128 query rows x 128 outs; streams 32 key-tiles of 64.
// Warp: 32M x 64N output slab -> B-fragments shared across 2 m16 subtiles.
#define PS 68
#define NS 136
#define SM_F (64*NS + 128*PS + 64 + 128)   // 17600 floats = 70400 B

__global__ __launch_bounds__(256, 1) void gat_attn_kernel(
    const int* __restrict__ adj,
    float* __restrict__ out)
{
    extern __shared__ float sm[];
    float*    nsh  = sm;                       // 64 x NS  (node tile, tf32 bits)
    float*    psh  = sm + 64 * NS;             // 128 x PS (P, tf32 bits)
    float*    fdsh = sm + 64 * NS + 128 * PS;  // 64
    float*    lsh  = fdsh + 64;                // 128
    uint32_t* nu   = (uint32_t*)nsh;
    uint32_t* pu   = (uint32_t*)psh;

    const int t  = threadIdx.x;
    const int b  = blockIdx.y;
    const int n0 = blockIdx.x * 128;

    // score-phase mapping: 2 lanes per row, 32 contiguous cols each
    const int sr = t >> 1;            // 0..127
    const int c0 = (t & 1) * 32;
    // mma-phase mapping: warp = 32M x 64N
    const int w   = t >> 5;
    const int wm  = w >> 1;           // 0..3 : rows wm*32..+32
    const int wn  = w & 1;            // 0..1 : cols wn*64..+64
    const int l   = t & 31;
    const int gid = l >> 2;
    const int tig = l & 3;

    float acc[2][8][4];
    #pragma unroll
    for (int mr = 0; mr < 2; mr++)
        #pragma unroll
        for (int nb = 0; nb < 8; nb++)
            #pragma unroll
            for (int j = 0; j < 4; j++) acc[mr][nb][j] = 0.f;

    const float fs = g_fsrc[b * NN + n0 + sr];
    const int*   adjr   = adj + ((size_t)b * NN + n0 + sr) * NN + c0;
    const float* nodesb = g_nodes + (size_t)b * NN * OUT_F;
    const float* fdb    = g_fdstb + b * NN;
    float lsum = 0.f;

    // ---- prefetch tile 0 into registers ----
    int4   av[8];
    float4 nv[8];
    float4 fdv;
    #pragma unroll
    for (int j = 0; j < 8; j++) av[j] = *(const int4*)&adjr[4 * j];
    #pragma unroll
    for (int j = 0; j < 8; j++) {
        int idx = t + 256 * j;
        int rr = idx >> 5, o4 = idx & 31;
        nv[j] = *(const float4*)&nodesb[(size_t)rr * OUT_F + o4 * 4];
    }
    if (t < 16) fdv = *(const float4*)&fdb[t * 4];

    for (int it = 0; it < 32; it++) {
        __syncthreads();   // previous mma done reading nsh/psh

        // ---- stage node tile + fd from prefetch regs ----
        #pragma unroll
        for (int j = 0; j < 8; j++) {
            int idx = t + 256 * j;
            int rr = idx >> 5, o4 = idx & 31;
            *(float4*)&nsh[rr * NS + o4 * 4] = nv[j];
        }
        if (t < 16) *(float4*)&fdsh[t * 4] = fdv;
        __syncthreads();

        // ---- scores -> p = exp(leakyrelu(s)) * mask ; write tf32 P ----
        #pragma unroll
        for (int j = 0; j < 8; j++) {
            float4 fd4 = *(float4*)&fdsh[c0 + 4 * j];
            uint4 pv;
            float s, p;
            s = fs + fd4.x; s = (s >= 0.f) ? s : 0.2f * s;
            p = (av[j].x > 0) ? __expf(s) : 0.f; lsum += p;
            asm("cvt.rna.tf32.f32 %0, %1;" : "=r"(pv.x) : "f"(p));
            s = fs + fd4.y; s = (s >= 0.f) ? s : 0.2f * s;
            p = (av[j].y > 0) ? __expf(s) : 0.f; lsum += p;
            asm("cvt.rna.tf32.f32 %0, %1;" : "=r"(pv.y) : "f"(p));
            s = fs + fd4.z; s = (s >= 0.f) ? s : 0.2f * s;
            p = (av[j].z > 0) ? __expf(s) : 0.f; lsum += p;
            asm("cvt.rna.tf32.f32 %0, %1;" : "=r"(pv.z) : "f"(p));
            s = fs + fd4.w; s = (s >= 0.f) ? s : 0.2f * s;
            p = (av[j].w > 0) ? __expf(s) : 0.f; lsum += p;
            asm("cvt.rna.tf32.f32 %0, %1;" : "=r"(pv.w) : "f"(p));
            *(uint4*)&pu[sr * PS + c0 + 4 * j] = pv;
        }

        // ---- prefetch next tile (hidden behind the upcoming mma) ----
        if (it < 31) {
            const int m1 = (it + 1) * 64;
            #pragma unroll
            for (int j = 0; j < 8; j++) av[j] = *(const int4*)&adjr[m1 + 4 * j];
            #pragma unroll
            for (int j = 0; j < 8; j++) {
                int idx = t + 256 * j;
                int rr = idx >> 5, o4 = idx & 31;
                nv[j] = *(const float4*)&nodesb[(size_t)(m1 + rr) * OUT_F + o4 * 4];
            }
            if (t < 16) fdv = *(const float4*)&fdb[m1 + t * 4];
        }
        __syncthreads();

        // ---- PV: warp computes 32x64; B-fragments reused across 2 m16 tiles ----
        #pragma unroll
        for (int kc = 0; kc < 8; kc++) {
            const int k0 = kc * 8;
            uint32_t A[2][4];
            #pragma unroll
            for (int mr = 0; mr < 2; mr++) {
                const int rb = wm * 32 + mr * 16;
                A[mr][0] = pu[(rb + gid)     * PS + k0 + tig];
                A[mr][1] = pu[(rb + gid + 8) * PS + k0 + tig];
                A[mr][2] = pu[(rb + gid)     * PS + k0 + tig + 4];
                A[mr][3] = pu[(rb + gid + 8) * PS + k0 + tig + 4];
            }
            #pragma unroll
            for (int nb = 0; nb < 8; nb++) {
                uint32_t b0 = nu[(k0 + tig)     * NS + wn * 64 + nb * 8 + gid];
                uint32_t b1 = nu[(k0 + tig + 4) * NS + wn * 64 + nb * 8 + gid];
                #pragma unroll
                for (int mr = 0; mr < 2; mr++) {
                    asm volatile(
                        "mma.sync.aligned.m16n8k8.row.col.f32.tf32.tf32.f32 "
                        "{%0,%1,%2,%3}, {%4,%5,%6,%7}, {%8,%9}, {%0,%1,%2,%3};\n"
                        : "+f"(acc[mr][nb][0]), "+f"(acc[mr][nb][1]),
                          "+f"(acc[mr][nb][2]), "+f"(acc[mr][nb][3])
                        : "r"(A[mr][0]), "r"(A[mr][1]), "r"(A[mr][2]), "r"(A[mr][3]),
                          "r"(b0), "r"(b1));
                }
            }
        }
    }

    // ---- row sums: combine the 2 lanes covering each row ----
    lsum += __shfl_xor_sync(0xffffffffu, lsum, 1);
    if ((t & 1) == 0) lsh[sr] = lsum;
    __syncthreads();

    // ---- epilogue: divide by l, store ----
    #pragma unroll
    for (int mr = 0; mr < 2; mr++) {
        const int r0 = wm * 32 + mr * 16 + gid;
        const int r1 = r0 + 8;
        float l0 = lsh[r0], l1 = lsh[r1];
        float inv0 = (l0 > 0.f) ? 1.f / l0 : 0.f;
        float inv1 = (l1 > 0.f) ? 1.f / l1 : 0.f;
        #pragma unroll
        for (int nb = 0; nb < 8; nb++) {
            int col = wn * 64 + nb * 8 + tig * 2;
            size_t ro0 = ((size_t)b * NN + n0 + r0) * OUT_F + col;
            size_t ro1 = ((size_t)b * NN + n0 + r1) * OUT_F + col;
            *(float2*)&out[ro0] = make_float2(acc[mr][nb][0] * inv0, acc[mr][nb][1] * inv0);
            *(float2*)&out[ro1] = make_float2(acc[mr][nb][2] * inv1, acc[mr][nb][3] * inv1);
        }
    }
}

// ---------------- launch ----------------
extern "C" void kernel_launch(void* const* d_in, const int* in_sizes, int n_in,
                              void* d_out, int out_size)
{
    const float* X   = (const float*)d_in[0];
    const int*   adj = (const int*)  d_in[1];
    const float* Ww  = (const float*)d_in[2];
    const float* Wb  = (const float*)d_in[3];
    const float* aw  = (const float*)d_in[4];
    const float* ab  = (const float*)d_in[5];
    float* out = (float*)d_out;

    static bool attr_set = false;
    if (!attr_set) {
        cudaFuncSetAttribute(gat_attn_kernel,
                             cudaFuncAttributeMaxDynamicSharedMemorySize,
                             SM_F * sizeof(float));
        attr_set = true;
    }

    transpose_W_kernel<<<128, 256>>>(Ww);
    node_transform_kernel<<<NROWS / 32, 256>>>(X, Wb, aw, ab);
    dim3 grid(NN / 128, BS);
    gat_attn_kernel<<<grid, 256, SM_F * sizeof(float)>>>(adj, out);
}

// round 6
// speedup vs baseline: 1.0002x; 1.0002x over previous
#include <cuda_runtime.h>
#include <math.h>
#include <stdint.h>

#define BS 8
#define NN 2048
#define IN_F 256
#define OUT_F 128
#define NROWS (BS * NN)   // 16384

// ---------------- scratch (static __device__, no allocations) ----------------
__device__ float g_WT[IN_F * OUT_F];             // W transposed: [k][o]
__device__ float g_nodes[(size_t)NROWS * OUT_F]; // 8 MB, tf32-rounded values
__device__ float g_fsrc[NROWS];
__device__ float g_fdstb[NROWS];                 // f_dst + a_b folded

// ---------------- kernel 0: transpose W (128x256 -> 256x128) ----------------
__global__ void transpose_W_kernel(const float* __restrict__ W) {
    int i = blockIdx.x * blockDim.x + threadIdx.x;
    int o = i >> 8;
    int k = i & 255;
    g_WT[k * OUT_F + o] = W[i];
}

// ---------------- kernel 1: nodes = X @ W^T + b, plus f_src/f_dst ----------------
__global__ __launch_bounds__(256) void node_transform_kernel(
    const float* __restrict__ X,
    const float* __restrict__ Wb,
    const float* __restrict__ aw,
    const float* __restrict__ ab)
{
    __shared__ float sIn[32 * 64];
    __shared__ float sW[64 * 128];

    const int t  = threadIdx.x;
    const int tx = t & 31;
    const int ty = t >> 5;
    const int R0 = blockIdx.x * 32;

    float acc[4][4];
    #pragma unroll
    for (int i = 0; i < 4; i++)
        #pragma unroll
        for (int j = 0; j < 4; j++) acc[i][j] = 0.f;

    for (int kc = 0; kc < 4; kc++) {
        const int k0 = kc * 64;
        __syncthreads();
        #pragma unroll
        for (int j = 0; j < 2; j++) {
            int f4 = t + 256 * j;
            int rr = f4 >> 4, c4 = f4 & 15;
            *(float4*)&sIn[rr * 64 + c4 * 4] =
                *(const float4*)&X[(size_t)(R0 + rr) * IN_F + k0 + c4 * 4];
        }
        #pragma unroll
        for (int j = 0; j < 8; j++) {
            int f4 = t + 256 * j;
            int kk = f4 >> 5, o4 = f4 & 31;
            *(float4*)&sW[kk * 128 + o4 * 4] =
                *(const float4*)&g_WT[(size_t)(k0 + kk) * OUT_F + o4 * 4];
        }
        __syncthreads();

        #pragma unroll
        for (int k4 = 0; k4 < 16; k4++) {
            float4 iv[4];
            #pragma unroll
            for (int i = 0; i < 4; i++)
                iv[i] = *(float4*)&sIn[(ty * 4 + i) * 64 + k4 * 4];
            #pragma unroll
            for (int kk = 0; kk < 4; kk++) {
                float4 wv = *(float4*)&sW[(k4 * 4 + kk) * 128 + tx * 4];
                #pragma unroll
                for (int i = 0; i < 4; i++) {
                    float xv = (kk == 0) ? iv[i].x : (kk == 1) ? iv[i].y
                             : (kk == 2) ? iv[i].z : iv[i].w;
                    acc[i][0] = fmaf(xv, wv.x, acc[i][0]);
                    acc[i][1] = fmaf(xv, wv.y, acc[i][1]);
                    acc[i][2] = fmaf(xv, wv.z, acc[i][2]);
                    acc[i][3] = fmaf(xv, wv.w, acc[i][3]);
                }
            }
        }
    }

    float bb[4], a1[4], a2[4];
    #pragma unroll
    for (int j = 0; j < 4; j++) {
        bb[j] = Wb[tx * 4 + j];
        a1[j] = aw[tx * 4 + j];
        a2[j] = aw[OUT_F + tx * 4 + j];
    }
    const float abv = ab[0];

    #pragma unroll
    for (int i = 0; i < 4; i++) {
        #pragma unroll
        for (int j = 0; j < 4; j++) acc[i][j] += bb[j];
        const int row = R0 + ty * 4 + i;

        float ps = acc[i][0]*a1[0] + acc[i][1]*a1[1] + acc[i][2]*a1[2] + acc[i][3]*a1[3];
        float pd = acc[i][0]*a2[0] + acc[i][1]*a2[1] + acc[i][2]*a2[2] + acc[i][3]*a2[3];
        #pragma unroll
        for (int off = 16; off > 0; off >>= 1) {
            ps += __shfl_xor_sync(0xffffffffu, ps, off);
            pd += __shfl_xor_sync(0xffffffffu, pd, off);
        }
        if (tx == 0) {
            g_fsrc[row]  = ps;
            g_fdstb[row] = pd + abv;
        }

        uint4 sv;
        asm("cvt.rna.tf32.f32 %0, %1;" : "=r"(sv.x) : "f"(acc[i][0]));
        asm("cvt.rna.tf32.f32 %0, %1;" : "=r"(sv.y) : "f"(acc[i][1]));
        asm("cvt.rna.tf32.f32 %0, %1;" : "=r"(sv.z) : "f"(acc[i][2]));
        asm("cvt.rna.tf32.f32 %0, %1;" : "=r"(sv.w) : "f"(acc[i][3]));
        *(uint4*)&g_nodes[(size_t)row * OUT_F + tx * 4] = sv;
    }
}

// ---------------- kernel 2: masked softmax + tf32 MMA PV, 128-row blocks ----------
// grid (16, 8) = 128 blocks (one wave), 256 threads (8 warps).
// Block: 128 query rows x 128 outs; streams 32 key-tiles of 64.
// Warp: 32M x 64N output slab -> B-fragments shared across 2 m16 subtiles.
#define PS 68
#define NS 136
#define SM_F (64*NS + 128*PS + 64 + 128)   // 17600 floats = 70400 B

__global__ __launch_bounds__(256, 1) void gat_attn_kernel(
    const int* __restrict__ adj,
    float* __restrict__ out)
{
    extern __shared__ float sm[];
    float*    nsh  = sm;                       // 64 x NS  (node tile, tf32 bits)
    float*    psh  = sm + 64 * NS;             // 128 x PS (P, tf32 bits)
    float*    fdsh = sm + 64 * NS + 128 * PS;  // 64
    float*    lsh  = fdsh + 64;                // 128
    uint32_t* nu   = (uint32_t*)nsh;
    uint32_t* pu   = (uint32_t*)psh;

    const int t  = threadIdx.x;
    const int b  = blockIdx.y;
    const int n0 = blockIdx.x * 128;

    // score-phase mapping: 2 lanes per row, 32 contiguous cols each
    const int sr = t >> 1;            // 0..127
    const int c0 = (t & 1) * 32;
    // mma-phase mapping: warp = 32M x 64N
    const int w   = t >> 5;
    const int wm  = w >> 1;           // 0..3 : rows wm*32..+32
    const int wn  = w & 1;            // 0..1 : cols wn*64..+64
    const int l   = t & 31;
    const int gid = l >> 2;
    const int tig = l & 3;

    float acc[2][8][4];
    #pragma unroll
    for (int mr = 0; mr < 2; mr++)
        #pragma unroll
        for (int nb = 0; nb < 8; nb++)
            #pragma unroll
            for (int j = 0; j < 4; j++) acc[mr][nb][j] = 0.f;

    const float fs = g_fsrc[b * NN + n0 + sr];
    const int*   adjr   = adj + ((size_t)b * NN + n0 + sr) * NN + c0;
    const float* nodesb = g_nodes + (size_t)b * NN * OUT_F;
    const float* fdb    = g_fdstb + b * NN;
    float lsum = 0.f;

    // ---- prefetch tile 0 into registers ----
    int4   av[8];
    float4 nv[8];
    float4 fdv;
    #pragma unroll
    for (int j = 0; j < 8; j++) av[j] = *(const int4*)&adjr[4 * j];
    #pragma unroll
    for (int j = 0; j < 8; j++) {
        int idx = t + 256 * j;
        int rr = idx >> 5, o4 = idx & 31;
        nv[j] = *(const float4*)&nodesb[(size_t)rr * OUT_F + o4 * 4];
    }
    if (t < 16) fdv = *(const float4*)&fdb[t * 4];

    for (int it = 0; it < 32; it++) {
        __syncthreads();   // previous mma done reading nsh/psh

        // ---- stage node tile + fd from prefetch regs ----
        #pragma unroll
        for (int j = 0; j < 8; j++) {
            int idx = t + 256 * j;
            int rr = idx >> 5, o4 = idx & 31;
            *(float4*)&nsh[rr * NS + o4 * 4] = nv[j];
        }
        if (t < 16) *(float4*)&fdsh[t * 4] = fdv;
        __syncthreads();

        // ---- scores -> p = exp(leakyrelu(s)) * mask ; write tf32 P ----
        #pragma unroll
        for (int j = 0; j < 8; j++) {
            float4 fd4 = *(float4*)&fdsh[c0 + 4 * j];
            uint4 pv;
            float s, p;
            s = fs + fd4.x; s = (s >= 0.f) ? s : 0.2f * s;
            p = (av[j].x > 0) ? __expf(s) : 0.f; lsum += p;
            asm("cvt.rna.tf32.f32 %0, %1;" : "=r"(pv.x) : "f"(p));
            s = fs + fd4.y; s = (s >= 0.f) ? s : 0.2f * s;
            p = (av[j].y > 0) ? __expf(s) : 0.f; lsum += p;
            asm("cvt.rna.tf32.f32 %0, %1;" : "=r"(pv.y) : "f"(p));
            s = fs + fd4.z; s = (s >= 0.f) ? s : 0.2f * s;
            p = (av[j].z > 0) ? __expf(s) : 0.f; lsum += p;
            asm("cvt.rna.tf32.f32 %0, %1;" : "=r"(pv.z) : "f"(p));
            s = fs + fd4.w; s = (s >= 0.f) ? s : 0.2f * s;
            p = (av[j].w > 0) ? __expf(s) : 0.f; lsum += p;
            asm("cvt.rna.tf32.f32 %0, %1;" : "=r"(pv.w) : "f"(p));
            *(uint4*)&pu[sr * PS + c0 + 4 * j] = pv;
        }

        // ---- prefetch next tile (hidden behind the upcoming mma) ----
        if (it < 31) {
            const int m1 = (it + 1) * 64;
            #pragma unroll
            for (int j = 0; j < 8; j++) av[j] = *(const int4*)&adjr[m1 + 4 * j];
            #pragma unroll
            for (int j = 0; j < 8; j++) {
                int idx = t + 256 * j;
                int rr = idx >> 5, o4 = idx & 31;
                nv[j] = *(const float4*)&nodesb[(size_t)(m1 + rr) * OUT_F + o4 * 4];
            }
            if (t < 16) fdv = *(const float4*)&fdb[m1 + t * 4];
        }
        __syncthreads();

        // ---- PV: warp computes 32x64; B-fragments reused across 2 m16 tiles ----
        #pragma unroll
        for (int kc = 0; kc < 8; kc++) {
            const int k0 = kc * 8;
            uint32_t A[2][4];
            #pragma unroll
            for (int mr = 0; mr < 2; mr++) {
                const int rb = wm * 32 + mr * 16;
                A[mr][0] = pu[(rb + gid)     * PS + k0 + tig];
                A[mr][1] = pu[(rb + gid + 8) * PS + k0 + tig];
                A[mr][2] = pu[(rb + gid)     * PS + k0 + tig + 4];
                A[mr][3] = pu[(rb + gid + 8) * PS + k0 + tig + 4];
            }
            #pragma unroll
            for (int nb = 0; nb < 8; nb++) {
                uint32_t b0 = nu[(k0 + tig)     * NS + wn * 64 + nb * 8 + gid];
                uint32_t b1 = nu[(k0 + tig + 4) * NS + wn * 64 + nb * 8 + gid];
                #pragma unroll
                for (int mr = 0; mr < 2; mr++) {
                    asm volatile(
                        "mma.sync.aligned.m16n8k8.row.col.f32.tf32.tf32.f32 "
                        "{%0,%1,%2,%3}, {%4,%5,%6,%7}, {%8,%9}, {%0,%1,%2,%3};\n"
                        : "+f"(acc[mr][nb][0]), "+f"(acc[mr][nb][1]),
                          "+f"(acc[mr][nb][2]), "+f"(acc[mr][nb][3])
                        : "r"(A[mr][0]), "r"(A[mr][1]), "r"(A[mr][2]), "r"(A[mr][3]),
                          "r"(b0), "r"(b1));
                }
            }
        }
    }

    // ---- row sums: combine the 2 lanes covering each row ----
    lsum += __shfl_xor_sync(0xffffffffu, lsum, 1);
    if ((t & 1) == 0) lsh[sr] = lsum;
    __syncthreads();

    // ---- epilogue: divide by l, store ----
    #pragma unroll
    for (int mr = 0; mr < 2; mr++) {
        const int r0 = wm * 32 + mr * 16 + gid;
        const int r1 = r0 + 8;
        float l0 = lsh[r0], l1 = lsh[r1];
        float inv0 = (l0 > 0.f) ? 1.f / l0 : 0.f;
        float inv1 = (l1 > 0.f) ? 1.f / l1 : 0.f;
        #pragma unroll
        for (int nb = 0; nb < 8; nb++) {
            int col = wn * 64 + nb * 8 + tig * 2;
            size_t ro0 = ((size_t)b * NN + n0 + r0) * OUT_F + col;
            size_t ro1 = ((size_t)b * NN + n0 + r1) * OUT_F + col;
            *(float2*)&out[ro0] = make_float2(acc[mr][nb][0] * inv0, acc[mr][nb][1] * inv0);
            *(float2*)&out[ro1] = make_float2(acc[mr][nb][2] * inv1, acc[mr][nb][3] * inv1);
        }
    }
}

// ---------------- launch ----------------
extern "C" void kernel_launch(void* const* d_in, const int* in_sizes, int n_in,
                              void* d_out, int out_size)
{
    const float* X   = (const float*)d_in[0];
    const int*   adj = (const int*)  d_in[1];
    const float* Ww  = (const float*)d_in[2];
    const float* Wb  = (const float*)d_in[3];
    const float* aw  = (const float*)d_in[4];
    const float* ab  = (const float*)d_in[5];
    float* out = (float*)d_out;

    static bool attr_set = false;
    if (!attr_set) {
        cudaFuncSetAttribute(gat_attn_kernel,
                             cudaFuncAttributeMaxDynamicSharedMemorySize,
                             SM_F * sizeof(float));
        attr_set = true;
    }

    transpose_W_kernel<<<128, 256>>>(Ww);
    node_transform_kernel<<<NROWS / 32, 256>>>(X, Wb, aw, ab);
    dim3 grid(NN / 128, BS);
    gat_attn_kernel<<<grid, 256, SM_F * sizeof(float)>>>(adj, out);
}

// round 7
// speedup vs baseline: 1.0787x; 1.0785x over previous
#include <cuda_runtime.h>
#include <math.h>
#include <stdint.h>

#define BS 8
#define NN 2048
#define IN_F 256
#define OUT_F 128
#define NROWS (BS * NN)   // 16384

// ---------------- scratch (static __device__, no allocations) ----------------
__device__ float g_WT[IN_F * OUT_F];             // W transposed: [k][o]
__device__ float g_nodes[(size_t)NROWS * OUT_F]; // 8 MB, tf32-rounded values
__device__ float g_fsrc[NROWS];
__device__ float g_fdstb[NROWS];                 // f_dst + a_b folded
__device__ float g_esrc1[NROWS];                 // exp(f_src)
__device__ float g_esrc2[NROWS];                 // exp(0.2*f_src)
__device__ float g_edst1[NROWS];                 // exp(f_dst + a_b)
__device__ float g_edst2[NROWS];                 // exp(0.2*(f_dst + a_b))

// ---------------- kernel 0: transpose W (128x256 -> 256x128) ----------------
__global__ void transpose_W_kernel(const float* __restrict__ W) {
    int i = blockIdx.x * blockDim.x + threadIdx.x;
    int o = i >> 8;
    int k = i & 255;
    g_WT[k * OUT_F + o] = W[i];
}

// ---------------- kernel 1: nodes = X @ W^T + b, f_src/f_dst + exp factors ------
__global__ __launch_bounds__(256) void node_transform_kernel(
    const float* __restrict__ X,
    const float* __restrict__ Wb,
    const float* __restrict__ aw,
    const float* __restrict__ ab)
{
    __shared__ float sIn[32 * 64];
    __shared__ float sW[64 * 128];

    const int t  = threadIdx.x;
    const int tx = t & 31;
    const int ty = t >> 5;
    const int R0 = blockIdx.x * 32;

    float acc[4][4];
    #pragma unroll
    for (int i = 0; i < 4; i++)
        #pragma unroll
        for (int j = 0; j < 4; j++) acc[i][j] = 0.f;

    for (int kc = 0; kc < 4; kc++) {
        const int k0 = kc * 64;
        __syncthreads();
        #pragma unroll
        for (int j = 0; j < 2; j++) {
            int f4 = t + 256 * j;
            int rr = f4 >> 4, c4 = f4 & 15;
            *(float4*)&sIn[rr * 64 + c4 * 4] =
                *(const float4*)&X[(size_t)(R0 + rr) * IN_F + k0 + c4 * 4];
        }
        #pragma unroll
        for (int j = 0; j < 8; j++) {
            int f4 = t + 256 * j;
            int kk = f4 >> 5, o4 = f4 & 31;
            *(float4*)&sW[kk * 128 + o4 * 4] =
                *(const float4*)&g_WT[(size_t)(k0 + kk) * OUT_F + o4 * 4];
        }
        __syncthreads();

        #pragma unroll
        for (int k4 = 0; k4 < 16; k4++) {
            float4 iv[4];
            #pragma unroll
            for (int i = 0; i < 4; i++)
                iv[i] = *(float4*)&sIn[(ty * 4 + i) * 64 + k4 * 4];
            #pragma unroll
            for (int kk = 0; kk < 4; kk++) {
                float4 wv = *(float4*)&sW[(k4 * 4 + kk) * 128 + tx * 4];
                #pragma unroll
                for (int i = 0; i < 4; i++) {
                    float xv = (kk == 0) ? iv[i].x : (kk == 1) ? iv[i].y
                             : (kk == 2) ? iv[i].z : iv[i].w;
                    acc[i][0] = fmaf(xv, wv.x, acc[i][0]);
                    acc[i][1] = fmaf(xv, wv.y, acc[i][1]);
                    acc[i][2] = fmaf(xv, wv.z, acc[i][2]);
                    acc[i][3] = fmaf(xv, wv.w, acc[i][3]);
                }
            }
        }
    }

    float bb[4], a1[4], a2[4];
    #pragma unroll
    for (int j = 0; j < 4; j++) {
        bb[j] = Wb[tx * 4 + j];
        a1[j] = aw[tx * 4 + j];
        a2[j] = aw[OUT_F + tx * 4 + j];
    }
    const float abv = ab[0];

    #pragma unroll
    for (int i = 0; i < 4; i++) {
        #pragma unroll
        for (int j = 0; j < 4; j++) acc[i][j] += bb[j];
        const int row = R0 + ty * 4 + i;

        float ps = acc[i][0]*a1[0] + acc[i][1]*a1[1] + acc[i][2]*a1[2] + acc[i][3]*a1[3];
        float pd = acc[i][0]*a2[0] + acc[i][1]*a2[1] + acc[i][2]*a2[2] + acc[i][3]*a2[3];
        #pragma unroll
        for (int off = 16; off > 0; off >>= 1) {
            ps += __shfl_xor_sync(0xffffffffu, ps, off);
            pd += __shfl_xor_sync(0xffffffffu, pd, off);
        }
        if (tx == 0) {
            float fdb = pd + abv;
            g_fsrc[row]  = ps;
            g_fdstb[row] = fdb;
            g_esrc1[row] = __expf(ps);
            g_esrc2[row] = __expf(0.2f * ps);
            g_edst1[row] = __expf(fdb);
            g_edst2[row] = __expf(0.2f * fdb);
        }

        uint4 sv;
        asm("cvt.rna.tf32.f32 %0, %1;" : "=r"(sv.x) : "f"(acc[i][0]));
        asm("cvt.rna.tf32.f32 %0, %1;" : "=r"(sv.y) : "f"(acc[i][1]));
        asm("cvt.rna.tf32.f32 %0, %1;" : "=r"(sv.z) : "f"(acc[i][2]));
        asm("cvt.rna.tf32.f32 %0, %1;" : "=r"(sv.w) : "f"(acc[i][3]));
        *(uint4*)&g_nodes[(size_t)row * OUT_F + tx * 4] = sv;
    }
}

// ---------------- kernel 2: factored masked softmax + tf32 MMA PV ----------------
// grid (32, 8) = 256 blocks, 256 threads (8 warps), 2 blocks/SM.
// Block: 64 query rows x 128 outs; streams 32 key-tiles of 64.
// p = adj ? ((s>=0) ? es1*ed1 : es2*ed2) : 0   — zero MUFU in the inner loop.
#define PS 68
#define NS 136
// nsh 64*NS | psh 64*PS | fdsh 64 | e1sh 64 | e2sh 64 | lsh 64
#define SM_F (64*NS + 64*PS + 4*64)   // 13312 floats = 53248 B

__global__ __launch_bounds__(256, 2) void gat_attn_kernel(
    const int* __restrict__ adj,
    float* __restrict__ out)
{
    extern __shared__ float sm[];
    float*    nsh  = sm;
    float*    psh  = sm + 64 * NS;
    float*    fdsh = sm + 64 * NS + 64 * PS;
    float*    e1sh = fdsh + 64;
    float*    e2sh = fdsh + 128;
    float*    lsh  = fdsh + 192;
    uint32_t* nu   = (uint32_t*)nsh;
    uint32_t* pu   = (uint32_t*)psh;

    const int t  = threadIdx.x;
    const int b  = blockIdx.y;
    const int n0 = blockIdx.x * 64;

    // score-phase mapping: 4 lanes per row, 16 contiguous cols each
    const int sr = t >> 2;
    const int c0 = (t & 3) * 16;
    // mma-phase mapping
    const int w   = t >> 5;
    const int wm  = w & 3;
    const int wn  = w >> 2;
    const int l   = t & 31;
    const int gid = l >> 2;
    const int tig = l & 3;

    float acc[8][4];
    #pragma unroll
    for (int nb = 0; nb < 8; nb++)
        #pragma unroll
        for (int j = 0; j < 4; j++) acc[nb][j] = 0.f;

    const int qrow = b * NN + n0 + sr;
    const float fs  = g_fsrc[qrow];
    const float es1 = g_esrc1[qrow];
    const float es2 = g_esrc2[qrow];
    const int*   adjr   = adj + ((size_t)b * NN + n0 + sr) * NN + c0;
    const float* nodesb = g_nodes + (size_t)b * NN * OUT_F;
    const float* fdb    = g_fdstb + b * NN;
    const float* ed1b   = g_edst1 + b * NN;
    const float* ed2b   = g_edst2 + b * NN;
    float lsum = 0.f;

    // ---- prefetch tile 0 into registers ----
    int4   av[4];
    float4 nv[8];
    float4 trip;           // t<16: fd, 16..31: ed1, 32..47: ed2
    #pragma unroll
    for (int j = 0; j < 4; j++) av[j] = *(const int4*)&adjr[4 * j];
    #pragma unroll
    for (int j = 0; j < 8; j++) {
        int idx = t + 256 * j;
        int rr = idx >> 5, o4 = idx & 31;
        nv[j] = *(const float4*)&nodesb[(size_t)rr * OUT_F + o4 * 4];
    }
    {
        const float* srcp = (t < 16) ? fdb : (t < 32) ? ed1b : ed2b;
        if (t < 48) trip = *(const float4*)&srcp[(t & 15) * 4];
    }

    for (int it = 0; it < 32; it++) {
        __syncthreads();   // previous mma done with nsh/psh

        // ---- stage node tile + factor triples from prefetch regs ----
        #pragma unroll
        for (int j = 0; j < 8; j++) {
            int idx = t + 256 * j;
            int rr = idx >> 5, o4 = idx & 31;
            *(float4*)&nsh[rr * NS + o4 * 4] = nv[j];
        }
        if (t < 48) {
            float* dstp = (t < 16) ? fdsh : (t < 32) ? e1sh : e2sh;
            *(float4*)&dstp[(t & 15) * 4] = trip;
        }
        __syncthreads();

        // ---- scores: p = adj ? (s>=0 ? es1*ed1 : es2*ed2) : 0 ----
        #pragma unroll
        for (int j = 0; j < 4; j++) {
            float4 fd4 = *(float4*)&fdsh[c0 + 4 * j];
            float4 e14 = *(float4*)&e1sh[c0 + 4 * j];
            float4 e24 = *(float4*)&e2sh[c0 + 4 * j];
            uint4 pv;
            float s, p;
            s = fs + fd4.x;
            p = (s >= 0.f) ? es1 * e14.x : es2 * e24.x;
            p = (av[j].x > 0) ? p : 0.f; lsum += p;
            asm("cvt.rna.tf32.f32 %0, %1;" : "=r"(pv.x) : "f"(p));
            s = fs + fd4.y;
            p = (s >= 0.f) ? es1 * e14.y : es2 * e24.y;
            p = (av[j].y > 0) ? p : 0.f; lsum += p;
            asm("cvt.rna.tf32.f32 %0, %1;" : "=r"(pv.y) : "f"(p));
            s = fs + fd4.z;
            p = (s >= 0.f) ? es1 * e14.z : es2 * e24.z;
            p = (av[j].z > 0) ? p : 0.f; lsum += p;
            asm("cvt.rna.tf32.f32 %0, %1;" : "=r"(pv.z) : "f"(p));
            s = fs + fd4.w;
            p = (s >= 0.f) ? es1 * e14.w : es2 * e24.w;
            p = (av[j].w > 0) ? p : 0.f; lsum += p;
            asm("cvt.rna.tf32.f32 %0, %1;" : "=r"(pv.w) : "f"(p));
            *(uint4*)&pu[sr * PS + c0 + 4 * j] = pv;
        }

        // ---- prefetch next tile (hidden behind upcoming mma) ----
        if (it < 31) {
            const int m1 = (it + 1) * 64;
            #pragma unroll
            for (int j = 0; j < 4; j++) av[j] = *(const int4*)&adjr[m1 + 4 * j];
            #pragma unroll
            for (int j = 0; j < 8; j++) {
                int idx = t + 256 * j;
                int rr = idx >> 5, o4 = idx & 31;
                nv[j] = *(const float4*)&nodesb[(size_t)(m1 + rr) * OUT_F + o4 * 4];
            }
            const float* srcp = (t < 16) ? fdb : (t < 32) ? ed1b : ed2b;
            if (t < 48) trip = *(const float4*)&srcp[m1 + (t & 15) * 4];
        }
        __syncthreads();

        // ---- PV: acc += P(16x64 per warp-row-group) @ N(64x64 per warp-col-half) ----
        #pragma unroll
        for (int kc = 0; kc < 8; kc++) {
            const int k0 = kc * 8;
            uint32_t a0 = pu[(wm * 16 + gid)     * PS + k0 + tig];
            uint32_t a1 = pu[(wm * 16 + gid + 8) * PS + k0 + tig];
            uint32_t a2 = pu[(wm * 16 + gid)     * PS + k0 + tig + 4];
            uint32_t a3 = pu[(wm * 16 + gid + 8) * PS + k0 + tig + 4];
            #pragma unroll
            for (int nb = 0; nb < 8; nb++) {
                uint32_t b0 = nu[(k0 + tig)     * NS + wn * 64 + nb * 8 + gid];
                uint32_t b1 = nu[(k0 + tig + 4) * NS + wn * 64 + nb * 8 + gid];
                asm volatile(
                    "mma.sync.aligned.m16n8k8.row.col.f32.tf32.tf32.f32 "
                    "{%0,%1,%2,%3}, {%4,%5,%6,%7}, {%8,%9}, {%0,%1,%2,%3};\n"
                    : "+f"(acc[nb][0]), "+f"(acc[nb][1]),
                      "+f"(acc[nb][2]), "+f"(acc[nb][3])
                    : "r"(a0), "r"(a1), "r"(a2), "r"(a3), "r"(b0), "r"(b1));
            }
        }
    }

    // ---- row sums: reduce the 4 lanes covering each row ----
    lsum += __shfl_xor_sync(0xffffffffu, lsum, 1);
    lsum += __shfl_xor_sync(0xffffffffu, lsum, 2);
    if ((t & 3) == 0) lsh[sr] = lsum;
    __syncthreads();

    // ---- epilogue: divide by l, store ----
    {
        const int r0 = wm * 16 + gid;
        const int r1 = r0 + 8;
        float l0 = lsh[r0], l1 = lsh[r1];
        float inv0 = (l0 > 0.f) ? 1.f / l0 : 0.f;
        float inv1 = (l1 > 0.f) ? 1.f / l1 : 0.f;
        #pragma unroll
        for (int nb = 0; nb < 8; nb++) {
            int col = wn * 64 + nb * 8 + tig * 2;
            size_t ro0 = ((size_t)b * NN + n0 + r0) * OUT_F + col;
            size_t ro1 = ((size_t)b * NN + n0 + r1) * OUT_F + col;
            *(float2*)&out[ro0] = make_float2(acc[nb][0] * inv0, acc[nb][1] * inv0);
            *(float2*)&out[ro1] = make_float2(acc[nb][2] * inv1, acc[nb][3] * inv1);
        }
    }
}

// ---------------- launch ----------------
extern "C" void kernel_launch(void* const* d_in, const int* in_sizes, int n_in,
                              void* d_out, int out_size)
{
    const float* X   = (const float*)d_in[0];
    const int*   adj = (const int*)  d_in[1];
    const float* Ww  = (const float*)d_in[2];
    const float* Wb  = (const float*)d_in[3];
    const float* aw  = (const float*)d_in[4];
    const float* ab  = (const float*)d_in[5];
    float* out = (float*)d_out;

    static bool attr_set = false;
    if (!attr_set) {
        cudaFuncSetAttribute(gat_attn_kernel,
                             cudaFuncAttributeMaxDynamicSharedMemorySize,
                             SM_F * sizeof(float));
        attr_set = true;
    }

    transpose_W_kernel<<<128, 256>>>(Ww);
    node_transform_kernel<<<NROWS / 32, 256>>>(X, Wb, aw, ab);
    dim3 grid(NN / 64, BS);
    gat_attn_kernel<<<grid, 256, SM_F * sizeof(float)>>>(adj, out);
}

// round 8
// speedup vs baseline: 1.1100x; 1.0290x over previous
#include <cuda_runtime.h>
#include <math.h>
#include <stdint.h>

#define BS 8
#define NN 2048
#define IN_F 256
#define OUT_F 128
#define NROWS (BS * NN)   // 16384

// ---------------- scratch (static __device__, no allocations) ----------------
__device__ float g_WT[IN_F * OUT_F];             // W transposed: [k][o]
__device__ float g_nodes[(size_t)NROWS * OUT_F]; // 8 MB, tf32-rounded values
__device__ float g_fsrc[NROWS];
__device__ float g_fdstb[NROWS];                 // f_dst + a_b folded

static __device__ __forceinline__ uint32_t smaddr(const void* p) {
    return (uint32_t)__cvta_generic_to_shared(p);
}
#define CP16(dst, src) \
    asm volatile("cp.async.cg.shared.global [%0], [%1], 16;\n" :: "r"(dst), "l"(src))
#define CP_COMMIT() asm volatile("cp.async.commit_group;\n" ::: "memory")
#define CP_WAIT0()  asm volatile("cp.async.wait_group 0;\n" ::: "memory")

// ---------------- kernel 0: transpose W (128x256 -> 256x128) ----------------
__global__ void transpose_W_kernel(const float* __restrict__ W) {
    int i = blockIdx.x * blockDim.x + threadIdx.x;
    int o = i >> 8;
    int k = i & 255;
    g_WT[k * OUT_F + o] = W[i];
}

// ---------------- kernel 1: nodes = X @ W^T + b, plus f_src/f_dst ----------------
__global__ __launch_bounds__(256) void node_transform_kernel(
    const float* __restrict__ X,
    const float* __restrict__ Wb,
    const float* __restrict__ aw,
    const float* __restrict__ ab)
{
    __shared__ float sIn[32 * 64];
    __shared__ float sW[64 * 128];

    const int t  = threadIdx.x;
    const int tx = t & 31;
    const int ty = t >> 5;
    const int R0 = blockIdx.x * 32;

    float acc[4][4];
    #pragma unroll
    for (int i = 0; i < 4; i++)
        #pragma unroll
        for (int j = 0; j < 4; j++) acc[i][j] = 0.f;

    for (int kc = 0; kc < 4; kc++) {
        const int k0 = kc * 64;
        __syncthreads();
        #pragma unroll
        for (int j = 0; j < 2; j++) {
            int f4 = t + 256 * j;
            int rr = f4 >> 4, c4 = f4 & 15;
            *(float4*)&sIn[rr * 64 + c4 * 4] =
                *(const float4*)&X[(size_t)(R0 + rr) * IN_F + k0 + c4 * 4];
        }
        #pragma unroll
        for (int j = 0; j < 8; j++) {
            int f4 = t + 256 * j;
            int kk = f4 >> 5, o4 = f4 & 31;
            *(float4*)&sW[kk * 128 + o4 * 4] =
                *(const float4*)&g_WT[(size_t)(k0 + kk) * OUT_F + o4 * 4];
        }
        __syncthreads();

        #pragma unroll
        for (int k4 = 0; k4 < 16; k4++) {
            float4 iv[4];
            #pragma unroll
            for (int i = 0; i < 4; i++)
                iv[i] = *(float4*)&sIn[(ty * 4 + i) * 64 + k4 * 4];
            #pragma unroll
            for (int kk = 0; kk < 4; kk++) {
                float4 wv = *(float4*)&sW[(k4 * 4 + kk) * 128 + tx * 4];
                #pragma unroll
                for (int i = 0; i < 4; i++) {
                    float xv = (kk == 0) ? iv[i].x : (kk == 1) ? iv[i].y
                             : (kk == 2) ? iv[i].z : iv[i].w;
                    acc[i][0] = fmaf(xv, wv.x, acc[i][0]);
                    acc[i][1] = fmaf(xv, wv.y, acc[i][1]);
                    acc[i][2] = fmaf(xv, wv.z, acc[i][2]);
                    acc[i][3] = fmaf(xv, wv.w, acc[i][3]);
                }
            }
        }
    }

    float bb[4], a1[4], a2[4];
    #pragma unroll
    for (int j = 0; j < 4; j++) {
        bb[j] = Wb[tx * 4 + j];
        a1[j] = aw[tx * 4 + j];
        a2[j] = aw[OUT_F + tx * 4 + j];
    }
    const float abv = ab[0];

    #pragma unroll
    for (int i = 0; i < 4; i++) {
        #pragma unroll
        for (int j = 0; j < 4; j++) acc[i][j] += bb[j];
        const int row = R0 + ty * 4 + i;

        float ps = acc[i][0]*a1[0] + acc[i][1]*a1[1] + acc[i][2]*a1[2] + acc[i][3]*a1[3];
        float pd = acc[i][0]*a2[0] + acc[i][1]*a2[1] + acc[i][2]*a2[2] + acc[i][3]*a2[3];
        #pragma unroll
        for (int off = 16; off > 0; off >>= 1) {
            ps += __shfl_xor_sync(0xffffffffu, ps, off);
            pd += __shfl_xor_sync(0xffffffffu, pd, off);
        }
        if (tx == 0) {
            g_fsrc[row]  = ps;
            g_fdstb[row] = pd + abv;
        }

        uint4 sv;
        asm("cvt.rna.tf32.f32 %0, %1;" : "=r"(sv.x) : "f"(acc[i][0]));
        asm("cvt.rna.tf32.f32 %0, %1;" : "=r"(sv.y) : "f"(acc[i][1]));
        asm("cvt.rna.tf32.f32 %0, %1;" : "=r"(sv.z) : "f"(acc[i][2]));
        asm("cvt.rna.tf32.f32 %0, %1;" : "=r"(sv.w) : "f"(acc[i][3]));
        *(uint4*)&g_nodes[(size_t)row * OUT_F + tx * 4] = sv;
    }
}

// ---------------- kernel 2: masked softmax + tf32 MMA PV, cp.async staging -------
// grid (32, 8) = 256 blocks, 256 threads (8 warps), 2 blocks/SM (smem-limited).
// Block: 64 query rows x 128 outs; streams 32 key-tiles of 64.
// Nodes+fd tiles double-buffered via cp.async; 2 barriers/tile.
#define PS 68
#define NS 136
// nsh[2] 64*NS each | psh 64*PS | fdsh[2] 64 each | lsh 64
#define SM_F (2*64*NS + 64*PS + 2*64 + 64)   // 21952 floats = 87808 B

__global__ __launch_bounds__(256) void gat_attn_kernel(
    const int* __restrict__ adj,
    float* __restrict__ out)
{
    extern __shared__ float sm[];
    float*    nsh0 = sm;
    float*    nsh1 = sm + 64 * NS;
    float*    psh  = sm + 2 * 64 * NS;
    float*    fdsh0 = psh + 64 * PS;
    float*    fdsh1 = fdsh0 + 64;
    float*    lsh   = fdsh0 + 128;
    uint32_t* pu   = (uint32_t*)psh;

    const int t  = threadIdx.x;
    const int b  = blockIdx.y;
    const int n0 = blockIdx.x * 64;

    // score-phase mapping: 4 lanes per row, 16 contiguous cols each
    const int sr = t >> 2;
    const int c0 = (t & 3) * 16;
    // mma-phase mapping
    const int w   = t >> 5;
    const int wm  = w & 3;
    const int wn  = w >> 2;
    const int l   = t & 31;
    const int gid = l >> 2;
    const int tig = l & 3;
    // staging mapping (8 float4 per thread)
    const int srr = t >> 5;          // base row (stride 8)
    const int so4 = t & 31;          // float4 col

    float acc[8][4];
    #pragma unroll
    for (int nb = 0; nb < 8; nb++)
        #pragma unroll
        for (int j = 0; j < 4; j++) acc[nb][j] = 0.f;

    const float fs = g_fsrc[b * NN + n0 + sr];
    const int*   adjr   = adj + ((size_t)b * NN + n0 + sr) * NN + c0;
    const float* nodesb = g_nodes + (size_t)b * NN * OUT_F;
    const float* fdb    = g_fdstb + b * NN;
    float lsum = 0.f;

    // ---- prologue: cp.async tile 0 into buf0, prefetch adj tile 0 ----
    #pragma unroll
    for (int j = 0; j < 8; j++) {
        int rr = srr + 8 * j;
        CP16(smaddr(&nsh0[rr * NS + so4 * 4]),
             &nodesb[(size_t)rr * OUT_F + so4 * 4]);
    }
    if (t < 16) CP16(smaddr(&fdsh0[t * 4]), &fdb[t * 4]);
    CP_COMMIT();

    int4 av[4];
    #pragma unroll
    for (int j = 0; j < 4; j++) av[j] = *(const int4*)&adjr[4 * j];

    for (int it = 0; it < 32; it++) {
        float*    nbuf = (it & 1) ? nsh1 : nsh0;
        float*    fbuf = (it & 1) ? fdsh1 : fdsh0;
        uint32_t* nub  = (uint32_t*)nbuf;

        CP_WAIT0();          // tile it landed (this thread's group)
        __syncthreads();     // visible block-wide; prev MMA done with psh/other buf

        // ---- issue cp.async for tile it+1 into the other buffer ----
        if (it < 31) {
            const int m1 = (it + 1) * 64;
            float* nnext = (it & 1) ? nsh0 : nsh1;
            float* fnext = (it & 1) ? fdsh0 : fdsh1;
            #pragma unroll
            for (int j = 0; j < 8; j++) {
                int rr = srr + 8 * j;
                CP16(smaddr(&nnext[rr * NS + so4 * 4]),
                     &nodesb[(size_t)(m1 + rr) * OUT_F + so4 * 4]);
            }
            if (t < 16) CP16(smaddr(&fnext[t * 4]), &fdb[m1 + t * 4]);
            CP_COMMIT();
        }

        // ---- scores -> p = exp(leakyrelu(s)) * mask ; write tf32 P ----
        #pragma unroll
        for (int j = 0; j < 4; j++) {
            float4 fd4 = *(float4*)&fbuf[c0 + 4 * j];
            uint4 pv;
            float s, p;
            s = fs + fd4.x; s = (s >= 0.f) ? s : 0.2f * s;
            p = (av[j].x > 0) ? __expf(s) : 0.f; lsum += p;
            asm("cvt.rna.tf32.f32 %0, %1;" : "=r"(pv.x) : "f"(p));
            s = fs + fd4.y; s = (s >= 0.f) ? s : 0.2f * s;
            p = (av[j].y > 0) ? __expf(s) : 0.f; lsum += p;
            asm("cvt.rna.tf32.f32 %0, %1;" : "=r"(pv.y) : "f"(p));
            s = fs + fd4.z; s = (s >= 0.f) ? s : 0.2f * s;
            p = (av[j].z > 0) ? __expf(s) : 0.f; lsum += p;
            asm("cvt.rna.tf32.f32 %0, %1;" : "=r"(pv.z) : "f"(p));
            s = fs + fd4.w; s = (s >= 0.f) ? s : 0.2f * s;
            p = (av[j].w > 0) ? __expf(s) : 0.f; lsum += p;
            asm("cvt.rna.tf32.f32 %0, %1;" : "=r"(pv.w) : "f"(p));
            *(uint4*)&pu[sr * PS + c0 + 4 * j] = pv;
        }

        // ---- prefetch adj regs for tile it+1 (slack: MMA + wait + sync) ----
        if (it < 31) {
            const int m1 = (it + 1) * 64;
            #pragma unroll
            for (int j = 0; j < 4; j++) av[j] = *(const int4*)&adjr[m1 + 4 * j];
        }
        __syncthreads();     // P visible

        // ---- PV: acc += P(16x64 per warp-row-group) @ N(64x64 per warp-col-half) ----
        #pragma unroll
        for (int kc = 0; kc < 8; kc++) {
            const int k0 = kc * 8;
            uint32_t a0 = pu[(wm * 16 + gid)     * PS + k0 + tig];
            uint32_t a1 = pu[(wm * 16 + gid + 8) * PS + k0 + tig];
            uint32_t a2 = pu[(wm * 16 + gid)     * PS + k0 + tig + 4];
            uint32_t a3 = pu[(wm * 16 + gid + 8) * PS + k0 + tig + 4];
            #pragma unroll
            for (int nb = 0; nb < 8; nb++) {
                uint32_t b0 = nub[(k0 + tig)     * NS + wn * 64 + nb * 8 + gid];
                uint32_t b1 = nub[(k0 + tig + 4) * NS + wn * 64 + nb * 8 + gid];
                asm volatile(
                    "mma.sync.aligned.m16n8k8.row.col.f32.tf32.tf32.f32 "
                    "{%0,%1,%2,%3}, {%4,%5,%6,%7}, {%8,%9}, {%0,%1,%2,%3};\n"
                    : "+f"(acc[nb][0]), "+f"(acc[nb][1]),
                      "+f"(acc[nb][2]), "+f"(acc[nb][3])
                    : "r"(a0), "r"(a1), "r"(a2), "r"(a3), "r"(b0), "r"(b1));
            }
        }
    }

    // ---- row sums: reduce the 4 lanes covering each row ----
    lsum += __shfl_xor_sync(0xffffffffu, lsum, 1);
    lsum += __shfl_xor_sync(0xffffffffu, lsum, 2);
    if ((t & 3) == 0) lsh[sr] = lsum;
    __syncthreads();

    // ---- epilogue: divide by l, store ----
    {
        const int r0 = wm * 16 + gid;
        const int r1 = r0 + 8;
        float l0 = lsh[r0], l1 = lsh[r1];
        float inv0 = (l0 > 0.f) ? 1.f / l0 : 0.f;
        float inv1 = (l1 > 0.f) ? 1.f / l1 : 0.f;
        #pragma unroll
        for (int nb = 0; nb < 8; nb++) {
            int col = wn * 64 + nb * 8 + tig * 2;
            size_t ro0 = ((size_t)b * NN + n0 + r0) * OUT_F + col;
            size_t ro1 = ((size_t)b * NN + n0 + r1) * OUT_F + col;
            *(float2*)&out[ro0] = make_float2(acc[nb][0] * inv0, acc[nb][1] * inv0);
            *(float2*)&out[ro1] = make_float2(acc[nb][2] * inv1, acc[nb][3] * inv1);
        }
    }
}

// ---------------- launch ----------------
extern "C" void kernel_launch(void* const* d_in, const int* in_sizes, int n_in,
                              void* d_out, int out_size)
{
    const float* X   = (const float*)d_in[0];
    const int*   adj = (const int*)  d_in[1];
    const float* Ww  = (const float*)d_in[2];
    const float* Wb  = (const float*)d_in[3];
    const float* aw  = (const float*)d_in[4];
    const float* ab  = (const float*)d_in[5];
    float* out = (float*)d_out;

    static bool attr_set = false;
    if (!attr_set) {
        cudaFuncSetAttribute(gat_attn_kernel,
                             cudaFuncAttributeMaxDynamicSharedMemorySize,
                             SM_F * sizeof(float));
        attr_set = true;
    }

    transpose_W_kernel<<<128, 256>>>(Ww);
    node_transform_kernel<<<NROWS / 32, 256>>>(X, Wb, aw, ab);
    dim3 grid(NN / 64, BS);
    gat_attn_kernel<<<grid, 256, SM_F * sizeof(float)>>>(adj, out);
}

// round 9
// speedup vs baseline: 1.1242x; 1.0128x over previous
#include <cuda_runtime.h>
#include <math.h>
#include <stdint.h>

#define BS 8
#define NN 2048
#define IN_F 256
#define OUT_F 128
#define NROWS (BS * NN)   // 16384

// ---------------- scratch (static __device__, no allocations) ----------------
__device__ float g_WT[IN_F * OUT_F];               // W transposed: [k][o]
__device__ float g_nodesT[(size_t)NROWS * OUT_F];  // [b][o][m], tf32-rounded
__device__ float g_fsrc[NROWS];
__device__ float g_fdstb[NROWS];                   // f_dst + a_b folded

static __device__ __forceinline__ uint32_t smaddr(const void* p) {
    return (uint32_t)__cvta_generic_to_shared(p);
}

// ---------------- kernel 0: transpose W (128x256 -> 256x128) ----------------
__global__ void transpose_W_kernel(const float* __restrict__ W) {
    int i = blockIdx.x * blockDim.x + threadIdx.x;
    int o = i >> 8;
    int k = i & 255;
    g_WT[k * OUT_F + o] = W[i];
}

// ---------------- kernel 1: nodes = X @ W^T + b; writes nodesT + f factors ------
__global__ __launch_bounds__(256) void node_transform_kernel(
    const float* __restrict__ X,
    const float* __restrict__ Wb,
    const float* __restrict__ aw,
    const float* __restrict__ ab)
{
    __shared__ float sIn[32 * 64];
    __shared__ float sW[64 * 128];   // reused as 128x33 transpose buffer at end

    const int t  = threadIdx.x;
    const int tx = t & 31;
    const int ty = t >> 5;
    const int R0 = blockIdx.x * 32;

    float acc[4][4];
    #pragma unroll
    for (int i = 0; i < 4; i++)
        #pragma unroll
        for (int j = 0; j < 4; j++) acc[i][j] = 0.f;

    for (int kc = 0; kc < 4; kc++) {
        const int k0 = kc * 64;
        __syncthreads();
        #pragma unroll
        for (int j = 0; j < 2; j++) {
            int f4 = t + 256 * j;
            int rr = f4 >> 4, c4 = f4 & 15;
            *(float4*)&sIn[rr * 64 + c4 * 4] =
                *(const float4*)&X[(size_t)(R0 + rr) * IN_F + k0 + c4 * 4];
        }
        #pragma unroll
        for (int j = 0; j < 8; j++) {
            int f4 = t + 256 * j;
            int kk = f4 >> 5, o4 = f4 & 31;
            *(float4*)&sW[kk * 128 + o4 * 4] =
                *(const float4*)&g_WT[(size_t)(k0 + kk) * OUT_F + o4 * 4];
        }
        __syncthreads();

        #pragma unroll
        for (int k4 = 0; k4 < 16; k4++) {
            float4 iv[4];
            #pragma unroll
            for (int i = 0; i < 4; i++)
                iv[i] = *(float4*)&sIn[(ty * 4 + i) * 64 + k4 * 4];
            #pragma unroll
            for (int kk = 0; kk < 4; kk++) {
                float4 wv = *(float4*)&sW[(k4 * 4 + kk) * 128 + tx * 4];
                #pragma unroll
                for (int i = 0; i < 4; i++) {
                    float xv = (kk == 0) ? iv[i].x : (kk == 1) ? iv[i].y
                             : (kk == 2) ? iv[i].z : iv[i].w;
                    acc[i][0] = fmaf(xv, wv.x, acc[i][0]);
                    acc[i][1] = fmaf(xv, wv.y, acc[i][1]);
                    acc[i][2] = fmaf(xv, wv.z, acc[i][2]);
                    acc[i][3] = fmaf(xv, wv.w, acc[i][3]);
                }
            }
        }
    }

    float bb[4], a1[4], a2[4];
    #pragma unroll
    for (int j = 0; j < 4; j++) {
        bb[j] = Wb[tx * 4 + j];
        a1[j] = aw[tx * 4 + j];
        a2[j] = aw[OUT_F + tx * 4 + j];
    }
    const float abv = ab[0];

    // bias + f reductions (full precision, matches reference)
    #pragma unroll
    for (int i = 0; i < 4; i++) {
        #pragma unroll
        for (int j = 0; j < 4; j++) acc[i][j] += bb[j];
        const int row = R0 + ty * 4 + i;

        float ps = acc[i][0]*a1[0] + acc[i][1]*a1[1] + acc[i][2]*a1[2] + acc[i][3]*a1[3];
        float pd = acc[i][0]*a2[0] + acc[i][1]*a2[1] + acc[i][2]*a2[2] + acc[i][3]*a2[3];
        #pragma unroll
        for (int off = 16; off > 0; off >>= 1) {
            ps += __shfl_xor_sync(0xffffffffu, ps, off);
            pd += __shfl_xor_sync(0xffffffffu, pd, off);
        }
        if (tx == 0) {
            g_fsrc[row]  = ps;
            g_fdstb[row] = pd + abv;
        }
    }

    // ---- transpose via smem (sW reused as [o][m] stride 33), write g_nodesT ----
    __syncthreads();
    #pragma unroll
    for (int i = 0; i < 4; i++)
        #pragma unroll
        for (int j = 0; j < 4; j++) {
            uint32_t v;
            asm("cvt.rna.tf32.f32 %0, %1;" : "=r"(v) : "f"(acc[i][j]));
            ((uint32_t*)sW)[(tx * 4 + j) * 33 + ty * 4 + i] = v;
        }
    __syncthreads();

    const int bb2 = R0 >> 11;
    const int nn0 = R0 & (NN - 1);
    float* dstT = g_nodesT + (size_t)bb2 * OUT_F * NN + nn0;
    #pragma unroll
    for (int j2 = 0; j2 < 4; j2++) {
        int f = t + 256 * j2;      // 0..1023
        int o = f >> 3;            // 0..127
        int m4 = f & 7;            // 0..7
        float4 v;
        v.x = sW[o * 33 + m4 * 4 + 0];
        v.y = sW[o * 33 + m4 * 4 + 1];
        v.z = sW[o * 33 + m4 * 4 + 2];
        v.w = sW[o * 33 + m4 * 4 + 3];
        *(float4*)&dstT[(size_t)o * NN + m4 * 4] = v;
    }
}

// ---------------- kernel 2: masked softmax + tf32 MMA PV with ldmatrix ----------
// grid (32, 8) = 256 blocks, 256 threads (8 warps), 2 blocks/SM.
// Block: 64 query rows x 128 outs; streams 32 key-tiles of 64.
// Node tile stored feature-major nshT[o][m]; A and B fragments via ldmatrix.x4.
#define PS 68
#define NT 68
// nshT 128*NT | psh 64*PS | fdsh 64 | lsh 64
#define SM_F (128*NT + 64*PS + 64 + 64)   // 13184 floats = 52736 B

__global__ __launch_bounds__(256) void gat_attn_kernel(
    const int* __restrict__ adj,
    float* __restrict__ out)
{
    extern __shared__ float sm[];
    float*    nshT = sm;                  // [o][m] o=0..127, m=0..63, stride NT
    float*    psh  = sm + 128 * NT;       // [mq][mk] stride PS
    float*    fdsh = sm + 128 * NT + 64 * PS;
    float*    lsh  = fdsh + 64;
    uint32_t* pu   = (uint32_t*)psh;

    const int t  = threadIdx.x;
    const int b  = blockIdx.y;
    const int n0 = blockIdx.x * 64;

    // score-phase mapping: 4 lanes per row, 16 contiguous cols each
    const int sr = t >> 2;
    const int c0 = (t & 3) * 16;
    // mma-phase mapping
    const int w   = t >> 5;
    const int wm  = w & 3;            // rows wm*16..+16
    const int wn  = w >> 2;           // cols wn*64..+64
    const int l   = t & 31;
    const int gid = l >> 2;
    const int tig = l & 3;

    float acc[8][4];
    #pragma unroll
    for (int nb = 0; nb < 8; nb++)
        #pragma unroll
        for (int j = 0; j < 4; j++) acc[nb][j] = 0.f;

    // ldmatrix per-lane base addresses (bytes); per kc add k0*4
    const int lrow8 = (l & 7) + 8 * ((l >> 3) & 1);
    const int lkoff = (l >> 4) * 4;
    const uint32_t aBase = smaddr(&psh[(wm * 16 + lrow8) * PS + lkoff]);
    uint32_t bBase[4];
    #pragma unroll
    for (int g = 0; g < 4; g++)
        bBase[g] = smaddr(&nshT[(wn * 64 + g * 16 + lrow8) * NT + lkoff]);

    const float fs = g_fsrc[b * NN + n0 + sr];
    const int*   adjr   = adj + ((size_t)b * NN + n0 + sr) * NN + c0;
    const float* nodesTb = g_nodesT + (size_t)b * OUT_F * NN;
    const float* fdb    = g_fdstb + b * NN;
    float lsum = 0.f;

    for (int m0 = 0; m0 < NN; m0 += 64) {
        // adjacency for this thread's 16 cols: 4 x int4, contiguous per thread
        int4 av[4];
        #pragma unroll
        for (int j = 0; j < 4; j++)
            av[j] = *(const int4*)&adjr[m0 + 4 * j];

        __syncthreads();   // previous mma done with nshT/psh

        // ---- stage node tile feature-major: 128 o-rows x 64 m (coalesced) ----
        #pragma unroll
        for (int j = 0; j < 8; j++) {
            int idx = t + 256 * j;           // 0..2047 float4s
            int o  = idx >> 4;               // 0..127
            int m4 = idx & 15;               // 0..15
            *(float4*)&nshT[o * NT + m4 * 4] =
                *(const float4*)&nodesTb[(size_t)o * NN + m0 + m4 * 4];
        }
        if (t < 16) *(float4*)&fdsh[t * 4] = *(const float4*)&fdb[m0 + t * 4];
        __syncthreads();

        // ---- scores -> p = exp(leakyrelu(s)) * mask ; write tf32 P ----
        #pragma unroll
        for (int j = 0; j < 4; j++) {
            float4 fd4 = *(float4*)&fdsh[c0 + 4 * j];
            uint4 pv;
            float s, p;
            s = fs + fd4.x; s = (s >= 0.f) ? s : 0.2f * s;
            p = (av[j].x > 0) ? __expf(s) : 0.f; lsum += p;
            asm("cvt.rna.tf32.f32 %0, %1;" : "=r"(pv.x) : "f"(p));
            s = fs + fd4.y; s = (s >= 0.f) ? s : 0.2f * s;
            p = (av[j].y > 0) ? __expf(s) : 0.f; lsum += p;
            asm("cvt.rna.tf32.f32 %0, %1;" : "=r"(pv.y) : "f"(p));
            s = fs + fd4.z; s = (s >= 0.f) ? s : 0.2f * s;
            p = (av[j].z > 0) ? __expf(s) : 0.f; lsum += p;
            asm("cvt.rna.tf32.f32 %0, %1;" : "=r"(pv.z) : "f"(p));
            s = fs + fd4.w; s = (s >= 0.f) ? s : 0.2f * s;
            p = (av[j].w > 0) ? __expf(s) : 0.f; lsum += p;
            asm("cvt.rna.tf32.f32 %0, %1;" : "=r"(pv.w) : "f"(p));
            *(uint4*)&pu[sr * PS + c0 + 4 * j] = pv;
        }
        __syncthreads();

        // ---- PV via ldmatrix: per kc 1 A-LDSM.x4 + 4 B-LDSM.x4 + 8 HMMA ----
        #pragma unroll
        for (int kc = 0; kc < 8; kc++) {
            const uint32_t kb = kc * 8 * 4;   // k0 in bytes
            uint32_t a0, a1, a2, a3;
            asm volatile(
                "ldmatrix.sync.aligned.m8n8.x4.shared.b16 {%0,%1,%2,%3}, [%4];\n"
                : "=r"(a0), "=r"(a1), "=r"(a2), "=r"(a3)
                : "r"(aBase + kb));
            #pragma unroll
            for (int g = 0; g < 4; g++) {
                uint32_t r0, r1, r2, r3;
                asm volatile(
                    "ldmatrix.sync.aligned.m8n8.x4.shared.b16 {%0,%1,%2,%3}, [%4];\n"
                    : "=r"(r0), "=r"(r1), "=r"(r2), "=r"(r3)
                    : "r"(bBase[g] + kb));
                asm volatile(
                    "mma.sync.aligned.m16n8k8.row.col.f32.tf32.tf32.f32 "
                    "{%0,%1,%2,%3}, {%4,%5,%6,%7}, {%8,%9}, {%0,%1,%2,%3};\n"
                    : "+f"(acc[2*g][0]), "+f"(acc[2*g][1]),
                      "+f"(acc[2*g][2]), "+f"(acc[2*g][3])
                    : "r"(a0), "r"(a1), "r"(a2), "r"(a3), "r"(r0), "r"(r2));
                asm volatile(
                    "mma.sync.aligned.m16n8k8.row.col.f32.tf32.tf32.f32 "
                    "{%0,%1,%2,%3}, {%4,%5,%6,%7}, {%8,%9}, {%0,%1,%2,%3};\n"
                    : "+f"(acc[2*g+1][0]), "+f"(acc[2*g+1][1]),
                      "+f"(acc[2*g+1][2]), "+f"(acc[2*g+1][3])
                    : "r"(a0), "r"(a1), "r"(a2), "r"(a3), "r"(r1), "r"(r3));
            }
        }
    }

    // ---- row sums: reduce the 4 lanes covering each row ----
    lsum += __shfl_xor_sync(0xffffffffu, lsum, 1);
    lsum += __shfl_xor_sync(0xffffffffu, lsum, 2);
    if ((t & 3) == 0) lsh[sr] = lsum;
    __syncthreads();

    // ---- epilogue: divide by l, store ----
    {
        const int r0 = wm * 16 + gid;
        const int r1 = r0 + 8;
        float l0 = lsh[r0], l1 = lsh[r1];
        float inv0 = (l0 > 0.f) ? 1.f / l0 : 0.f;
        float inv1 = (l1 > 0.f) ? 1.f / l1 : 0.f;
        #pragma unroll
        for (int nb = 0; nb < 8; nb++) {
            int col = wn * 64 + nb * 8 + tig * 2;
            size_t ro0 = ((size_t)b * NN + n0 + r0) * OUT_F + col;
            size_t ro1 = ((size_t)b * NN + n0 + r1) * OUT_F + col;
            *(float2*)&out[ro0] = make_float2(acc[nb][0] * inv0, acc[nb][1] * inv0);
            *(float2*)&out[ro1] = make_float2(acc[nb][2] * inv1, acc[nb][3] * inv1);
        }
    }
}

// ---------------- launch ----------------
extern "C" void kernel_launch(void* const* d_in, const int* in_sizes, int n_in,
                              void* d_out, int out_size)
{
    const float* X   = (const float*)d_in[0];
    const int*   adj = (const int*)  d_in[1];
    const float* Ww  = (const float*)d_in[2];
    const float* Wb  = (const float*)d_in[3];
    const float* aw  = (const float*)d_in[4];
    const float* ab  = (const float*)d_in[5];
    float* out = (float*)d_out;

    static bool attr_set = false;
    if (!attr_set) {
        cudaFuncSetAttribute(gat_attn_kernel,
                             cudaFuncAttributeMaxDynamicSharedMemorySize,
                             SM_F * sizeof(float));
        attr_set = true;
    }

    transpose_W_kernel<<<128, 256>>>(Ww);
    node_transform_kernel<<<NROWS / 32, 256>>>(X, Wb, aw, ab);
    dim3 grid(NN / 64, BS);
    gat_attn_kernel<<<grid, 256, SM_F * sizeof(float)>>>(adj, out);
}

// round 10
// speedup vs baseline: 1.4331x; 1.2748x over previous
#include <cuda_runtime.h>
#include <cuda_fp16.h>
#include <math.h>
#include <stdint.h>

#define BS 8
#define NN 2048
#define IN_F 256
#define OUT_F 128
#define NROWS (BS * NN)   // 16384

// ---------------- scratch (static __device__, no allocations) ----------------
__device__ float  g_WT[IN_F * OUT_F];                 // W transposed: [k][o]
__device__ __half g_nodes_h[(size_t)NROWS * OUT_F];   // fp16 nodes, row-major
__device__ float  g_fsrc[NROWS];
__device__ float  g_fdstb[NROWS];                     // f_dst + a_b folded

static __device__ __forceinline__ uint32_t smaddr(const void* p) {
    return (uint32_t)__cvta_generic_to_shared(p);
}

// ---------------- kernel 0: transpose W (128x256 -> 256x128) ----------------
__global__ void transpose_W_kernel(const float* __restrict__ W) {
    int i = blockIdx.x * blockDim.x + threadIdx.x;
    int o = i >> 8;
    int k = i & 255;
    g_WT[k * OUT_F + o] = W[i];
}

// ---------------- kernel 1: nodes = X @ W^T + b, f_src/f_dst; fp16 nodes --------
__global__ __launch_bounds__(256) void node_transform_kernel(
    const float* __restrict__ X,
    const float* __restrict__ Wb,
    const float* __restrict__ aw,
    const float* __restrict__ ab)
{
    __shared__ float sIn[32 * 64];
    __shared__ float sW[64 * 128];

    const int t  = threadIdx.x;
    const int tx = t & 31;
    const int ty = t >> 5;
    const int R0 = blockIdx.x * 32;

    float acc[4][4];
    #pragma unroll
    for (int i = 0; i < 4; i++)
        #pragma unroll
        for (int j = 0; j < 4; j++) acc[i][j] = 0.f;

    for (int kc = 0; kc < 4; kc++) {
        const int k0 = kc * 64;
        __syncthreads();
        #pragma unroll
        for (int j = 0; j < 2; j++) {
            int f4 = t + 256 * j;
            int rr = f4 >> 4, c4 = f4 & 15;
            *(float4*)&sIn[rr * 64 + c4 * 4] =
                *(const float4*)&X[(size_t)(R0 + rr) * IN_F + k0 + c4 * 4];
        }
        #pragma unroll
        for (int j = 0; j < 8; j++) {
            int f4 = t + 256 * j;
            int kk = f4 >> 5, o4 = f4 & 31;
            *(float4*)&sW[kk * 128 + o4 * 4] =
                *(const float4*)&g_WT[(size_t)(k0 + kk) * OUT_F + o4 * 4];
        }
        __syncthreads();

        #pragma unroll
        for (int k4 = 0; k4 < 16; k4++) {
            float4 iv[4];
            #pragma unroll
            for (int i = 0; i < 4; i++)
                iv[i] = *(float4*)&sIn[(ty * 4 + i) * 64 + k4 * 4];
            #pragma unroll
            for (int kk = 0; kk < 4; kk++) {
                float4 wv = *(float4*)&sW[(k4 * 4 + kk) * 128 + tx * 4];
                #pragma unroll
                for (int i = 0; i < 4; i++) {
                    float xv = (kk == 0) ? iv[i].x : (kk == 1) ? iv[i].y
                             : (kk == 2) ? iv[i].z : iv[i].w;
                    acc[i][0] = fmaf(xv, wv.x, acc[i][0]);
                    acc[i][1] = fmaf(xv, wv.y, acc[i][1]);
                    acc[i][2] = fmaf(xv, wv.z, acc[i][2]);
                    acc[i][3] = fmaf(xv, wv.w, acc[i][3]);
                }
            }
        }
    }

    float bb[4], a1[4], a2[4];
    #pragma unroll
    for (int j = 0; j < 4; j++) {
        bb[j] = Wb[tx * 4 + j];
        a1[j] = aw[tx * 4 + j];
        a2[j] = aw[OUT_F + tx * 4 + j];
    }
    const float abv = ab[0];

    #pragma unroll
    for (int i = 0; i < 4; i++) {
        #pragma unroll
        for (int j = 0; j < 4; j++) acc[i][j] += bb[j];
        const int row = R0 + ty * 4 + i;

        // f reductions use FULL precision nodes (matches reference)
        float ps = acc[i][0]*a1[0] + acc[i][1]*a1[1] + acc[i][2]*a1[2] + acc[i][3]*a1[3];
        float pd = acc[i][0]*a2[0] + acc[i][1]*a2[1] + acc[i][2]*a2[2] + acc[i][3]*a2[3];
        #pragma unroll
        for (int off = 16; off > 0; off >>= 1) {
            ps += __shfl_xor_sync(0xffffffffu, ps, off);
            pd += __shfl_xor_sync(0xffffffffu, pd, off);
        }
        if (tx == 0) {
            g_fsrc[row]  = ps;
            g_fdstb[row] = pd + abv;
        }

        // store nodes as fp16 (11-bit mantissa, same as tf32)
        __half2 h01 = __floats2half2_rn(acc[i][0], acc[i][1]);
        __half2 h23 = __floats2half2_rn(acc[i][2], acc[i][3]);
        uint2 sv = make_uint2(*(uint32_t*)&h01, *(uint32_t*)&h23);
        *(uint2*)&g_nodes_h[(size_t)row * OUT_F + tx * 4] = sv;
    }
}

// ---------------- kernel 2: masked softmax + fp16 MMA PV -------------------------
// grid (32, 8) = 256 blocks, 256 threads (8 warps).
// Block: 64 query rows x 128 outs; streams 32 key-tiles of 64.
// P (fp16) and nodes (fp16) in smem; PV via m16n8k16 f16 MMA w/ fp32 accum.
#define PSH 72     // psh stride in halves
#define NSH 136    // node tile stride in halves
// halves: nsh 64*NSH (8704) | psh 64*PSH (4608) ; floats: fdsh 64 | lsh 64
#define SM_BYTES ((64*NSH + 64*PSH) * 2 + 128 * 4)   // 27136 B

__global__ __launch_bounds__(256) void gat_attn_kernel(
    const int* __restrict__ adj,
    float* __restrict__ out)
{
    extern __shared__ char smraw[];
    __half* nsh  = (__half*)smraw;                     // [m_key][o] stride NSH
    __half* psh  = nsh + 64 * NSH;                     // [m_q][m_key] stride PSH
    float*  fdsh = (float*)(psh + 64 * PSH);
    float*  lsh  = fdsh + 64;

    const int t  = threadIdx.x;
    const int b  = blockIdx.y;
    const int n0 = blockIdx.x * 64;

    // score-phase mapping: 4 lanes per row, 16 contiguous cols each
    const int sr = t >> 2;
    const int c0 = (t & 3) * 16;   // in halves/cols
    // mma-phase mapping
    const int w   = t >> 5;
    const int wm  = w & 3;            // rows wm*16..+16
    const int wn  = w >> 2;           // cols wn*64..+64
    const int l   = t & 31;
    const int gid = l >> 2;
    const int tig = l & 3;

    float acc[8][4];
    #pragma unroll
    for (int nb = 0; nb < 8; nb++)
        #pragma unroll
        for (int j = 0; j < 4; j++) acc[nb][j] = 0.f;

    // ldmatrix lane addresses
    const int lrow = (l & 7) + 8 * ((l >> 3) & 1);   // 0..15
    const int lcol = 8 * (l >> 4);                   // 0 or 8
    const uint32_t aBase = smaddr(&psh[(wm * 16 + lrow) * PSH + lcol]);
    uint32_t bBase[4];
    #pragma unroll
    for (int g = 0; g < 4; g++)
        bBase[g] = smaddr(&nsh[lrow * NSH + wn * 64 + g * 16 + lcol]);

    const float fs = g_fsrc[b * NN + n0 + sr];
    const int*    adjr   = adj + ((size_t)b * NN + n0 + sr) * NN + c0;
    const __half* nodesb = g_nodes_h + (size_t)b * NN * OUT_F;
    const float*  fdb    = g_fdstb + b * NN;
    float lsum = 0.f;

    for (int m0 = 0; m0 < NN; m0 += 64) {
        // adjacency for this thread's 16 cols (contiguous per thread)
        int4 av[4];
        #pragma unroll
        for (int j = 0; j < 4; j++)
            av[j] = *(const int4*)&adjr[m0 + 4 * j];

        __syncthreads();   // previous mma done with nsh/psh

        // ---- stage node tile: 64 rows x 128 halves (256B/row), 4 uint4/thread ----
        #pragma unroll
        for (int j = 0; j < 4; j++) {
            int idx = t + 256 * j;          // 0..1023 16B-chunks
            int rr = idx >> 4;              // 0..63
            int c8 = (idx & 15) * 8;        // half offset
            *(uint4*)&nsh[rr * NSH + c8] =
                *(const uint4*)&nodesb[(size_t)(m0 + rr) * OUT_F + c8];
        }
        if (t < 16) *(float4*)&fdsh[t * 4] = *(const float4*)&fdb[m0 + t * 4];
        __syncthreads();

        // ---- scores -> p = exp(leakyrelu(s)) * mask ; write fp16 P ----
        #pragma unroll
        for (int j = 0; j < 4; j++) {
            float4 fd4 = *(float4*)&fdsh[c0 + 4 * j];
            float s, p0, p1, p2, p3;
            s = fs + fd4.x; s = (s >= 0.f) ? s : 0.2f * s;
            p0 = (av[j].x > 0) ? __expf(s) : 0.f; lsum += p0;
            s = fs + fd4.y; s = (s >= 0.f) ? s : 0.2f * s;
            p1 = (av[j].y > 0) ? __expf(s) : 0.f; lsum += p1;
            s = fs + fd4.z; s = (s >= 0.f) ? s : 0.2f * s;
            p2 = (av[j].z > 0) ? __expf(s) : 0.f; lsum += p2;
            s = fs + fd4.w; s = (s >= 0.f) ? s : 0.2f * s;
            p3 = (av[j].w > 0) ? __expf(s) : 0.f; lsum += p3;
            __half2 h01 = __floats2half2_rn(p0, p1);
            __half2 h23 = __floats2half2_rn(p2, p3);
            uint2 pv = make_uint2(*(uint32_t*)&h01, *(uint32_t*)&h23);
            *(uint2*)&psh[sr * PSH + c0 + 4 * j] = pv;
        }
        __syncthreads();

        // ---- PV: per kc (K=16): 1 A-LDSM.x4 + 4 B-LDSM.x4.trans + 8 HMMA ----
        #pragma unroll
        for (int kc = 0; kc < 4; kc++) {
            const uint32_t aOff = kc * 16 * 2;            // 16 halves
            const uint32_t bOff = kc * 16 * NSH * 2;      // 16 rows
            uint32_t a0, a1, a2, a3;
            asm volatile(
                "ldmatrix.sync.aligned.m8n8.x4.shared.b16 {%0,%1,%2,%3}, [%4];\n"
                : "=r"(a0), "=r"(a1), "=r"(a2), "=r"(a3)
                : "r"(aBase + aOff));
            #pragma unroll
            for (int g = 0; g < 4; g++) {
                uint32_t r0, r1, r2, r3;
                asm volatile(
                    "ldmatrix.sync.aligned.m8n8.x4.trans.shared.b16 {%0,%1,%2,%3}, [%4];\n"
                    : "=r"(r0), "=r"(r1), "=r"(r2), "=r"(r3)
                    : "r"(bBase[g] + bOff));
                asm volatile(
                    "mma.sync.aligned.m16n8k16.row.col.f32.f16.f16.f32 "
                    "{%0,%1,%2,%3}, {%4,%5,%6,%7}, {%8,%9}, {%0,%1,%2,%3};\n"
                    : "+f"(acc[2*g][0]), "+f"(acc[2*g][1]),
                      "+f"(acc[2*g][2]), "+f"(acc[2*g][3])
                    : "r"(a0), "r"(a1), "r"(a2), "r"(a3), "r"(r0), "r"(r1));
                asm volatile(
                    "mma.sync.aligned.m16n8k16.row.col.f32.f16.f16.f32 "
                    "{%0,%1,%2,%3}, {%4,%5,%6,%7}, {%8,%9}, {%0,%1,%2,%3};\n"
                    : "+f"(acc[2*g+1][0]), "+f"(acc[2*g+1][1]),
                      "+f"(acc[2*g+1][2]), "+f"(acc[2*g+1][3])
                    : "r"(a0), "r"(a1), "r"(a2), "r"(a3), "r"(r2), "r"(r3));
            }
        }
    }

    // ---- row sums: reduce the 4 lanes covering each row ----
    lsum += __shfl_xor_sync(0xffffffffu, lsum, 1);
    lsum += __shfl_xor_sync(0xffffffffu, lsum, 2);
    if ((t & 3) == 0) lsh[sr] = lsum;
    __syncthreads();

    // ---- epilogue: divide by l, store ----
    {
        const int r0 = wm * 16 + gid;
        const int r1 = r0 + 8;
        float l0 = lsh[r0], l1 = lsh[r1];
        float inv0 = (l0 > 0.f) ? 1.f / l0 : 0.f;
        float inv1 = (l1 > 0.f) ? 1.f / l1 : 0.f;
        #pragma unroll
        for (int nb = 0; nb < 8; nb++) {
            int col = wn * 64 + nb * 8 + tig * 2;
            size_t ro0 = ((size_t)b * NN + n0 + r0) * OUT_F + col;
            size_t ro1 = ((size_t)b * NN + n0 + r1) * OUT_F + col;
            *(float2*)&out[ro0] = make_float2(acc[nb][0] * inv0, acc[nb][1] * inv0);
            *(float2*)&out[ro1] = make_float2(acc[nb][2] * inv1, acc[nb][3] * inv1);
        }
    }
}

// ---------------- launch ----------------
extern "C" void kernel_launch(void* const* d_in, const int* in_sizes, int n_in,
                              void* d_out, int out_size)
{
    const float* X   = (const float*)d_in[0];
    const int*   adj = (const int*)  d_in[1];
    const float* Ww  = (const float*)d_in[2];
    const float* Wb  = (const float*)d_in[3];
    const float* aw  = (const float*)d_in[4];
    const float* ab  = (const float*)d_in[5];
    float* out = (float*)d_out;

    static bool attr_set = false;
    if (!attr_set) {
        cudaFuncSetAttribute(gat_attn_kernel,
                             cudaFuncAttributeMaxDynamicSharedMemorySize,
                             SM_BYTES);
        attr_set = true;
    }

    transpose_W_kernel<<<128, 256>>>(Ww);
    node_transform_kernel<<<NROWS / 32, 256>>>(X, Wb, aw, ab);
    dim3 grid(NN / 64, BS);
    gat_attn_kernel<<<grid, 256, SM_BYTES>>>(adj, out);
}